// round 9
// baseline (speedup 1.0000x reference)
#include <cuda_runtime.h>
#include <cuda_bf16.h>
#include <math.h>
#include <cstdint>

// ---------------------------------------------------------------------------
// SelectiveStateSpace: B=8, S=2048, D_MODEL=1024, N=64
//   wconv    : W[192,1024] fp32 -> bf16 hi/lo split
//   proj_mma : ldmatrix + mma.sync bf16 3-term GEMM  D = X @ Wcat^T
//   scan1    : per-chunk local scan (zero init) -> h_end, sum(delta)
//   scan3    : lookback -> h_start, rescan, emit y
// Scan: 1024-thr blocks cover all 64 i (16 lanes/i, 4 j's/lane), grid 128,
// 4096 warps total; u/C read exactly once per chunk.
// ---------------------------------------------------------------------------

#define BQ   8
#define SQ   2048
#define DM   1024
#define NS   64
#define ROWS (BQ * SQ)        // 16384
#define RQ   (BQ * NS)        // 512
#define GQ   16               // chunks per row
#define LQ   (SQ / GQ)        // 128 steps per chunk
#define TS   16
#define NTIL (LQ / TS)        // 8

#define MT   128
#define NTOT 192
#define KC   32
#define NKC  (DM / KC)        // 32

#define LOG2E 1.4426950408889634f

// proj smem geometry (bytes): rows padded to 80B for ldmatrix
#define ROWB   80
#define A_TERM (MT * ROWB)
#define B_TERM (NTOT * ROWB)
#define A_OFF  0
#define B_OFF  (2 * A_TERM)
#define STG_SZ (2 * A_TERM + 2 * B_TERM)
#define SMEM_MMA (2 * STG_SZ)

// scratch (device globals; no allocation allowed)
__device__ float g_delta[ROWS * NS];
__device__ float g_u[ROWS * NS];
__device__ float g_c[ROWS * NS];
__device__ float g_hend[RQ * GQ * NS];
__device__ float g_dsum[RQ * GQ];
__device__ uint4 g_Whi4[NTOT * DM / 8];
__device__ uint4 g_Wlo4[NTOT * DM / 8];

// ------------------------------ helpers -------------------------------------
__device__ __forceinline__ uint32_t smem_u32(const void* p) {
    uint32_t a;
    asm("{ .reg .u64 t; cvta.to.shared.u64 t, %1; cvt.u32.u64 %0, t; }"
        : "=r"(a) : "l"(p));
    return a;
}
__device__ __forceinline__ float ex2(float x) {
    float r;
    asm("ex2.approx.ftz.f32 %0, %1;" : "=f"(r) : "f"(x));
    return r;
}
__device__ __forceinline__ float softplus_f(float v) {
    return (v > 20.0f) ? v : log1pf(expf(v));
}
__device__ __forceinline__ uint32_t hipack(float a, float b) {
    __nv_bfloat162 h;
    h.x = __float2bfloat16(a);
    h.y = __float2bfloat16(b);
    return *(uint32_t*)&h;
}
__device__ __forceinline__ uint32_t lopack(float a, float b) {
    __nv_bfloat16 ha = __float2bfloat16(a), hb = __float2bfloat16(b);
    __nv_bfloat162 h;
    h.x = __float2bfloat16(a - __bfloat162float(ha));
    h.y = __float2bfloat16(b - __bfloat162float(hb));
    return *(uint32_t*)&h;
}
__device__ __forceinline__ void ldsm4(uint32_t* r, uint32_t addr) {
    asm volatile("ldmatrix.sync.aligned.m8n8.x4.shared.b16 {%0,%1,%2,%3}, [%4];"
                 : "=r"(r[0]), "=r"(r[1]), "=r"(r[2]), "=r"(r[3]) : "r"(addr));
}
__device__ __forceinline__ void mma16816(float* c, const uint32_t* a, const uint32_t* b) {
    asm volatile(
        "mma.sync.aligned.m16n8k16.row.col.f32.bf16.bf16.f32 "
        "{%0,%1,%2,%3}, {%4,%5,%6,%7}, {%8,%9}, {%0,%1,%2,%3};"
        : "+f"(c[0]), "+f"(c[1]), "+f"(c[2]), "+f"(c[3])
        : "r"(a[0]), "r"(a[1]), "r"(a[2]), "r"(a[3]), "r"(b[0]), "r"(b[1]));
}

// ------------------------------ W conversion --------------------------------
__global__ void __launch_bounds__(256, 1)
wconv_kernel(const float* __restrict__ Wd, const float* __restrict__ Wb,
             const float* __restrict__ Wc) {
    int gi = blockIdx.x * 256 + threadIdx.x;
    int row = gi >> 7;
    int k8  = (gi & 127) * 8;
    const float* src = (row < 64) ? (Wd + (size_t)row * DM)
                    : (row < 128) ? (Wb + (size_t)(row - 64) * DM)
                                  : (Wc + (size_t)(row - 128) * DM);
    float f[8];
    *(float4*)&f[0] = *(const float4*)(src + k8);
    *(float4*)&f[4] = *(const float4*)(src + k8 + 4);
    uint4 hi, lo;
    hi.x = hipack(f[0], f[1]); hi.y = hipack(f[2], f[3]);
    hi.z = hipack(f[4], f[5]); hi.w = hipack(f[6], f[7]);
    lo.x = lopack(f[0], f[1]); lo.y = lopack(f[2], f[3]);
    lo.z = lopack(f[4], f[5]); lo.w = lopack(f[6], f[7]);
    g_Whi4[gi] = hi;
    g_Wlo4[gi] = lo;
}

// ------------------------------ proj (mma.sync) -----------------------------
__global__ void __launch_bounds__(256, 1)
proj_mma_kernel(const float* __restrict__ x,
                const float* __restrict__ bd, const float* __restrict__ bb,
                const float* __restrict__ bc) {
    extern __shared__ char smem[];
    const uint32_t sb = smem_u32(smem);
    const int tid    = threadIdx.x;
    const int lane   = tid & 31;
    const int warp   = tid >> 5;
    const int warp_m = warp >> 2;
    const int warp_n = warp & 3;
    const int m0     = blockIdx.x * MT;

    float acc[4][6][4];
#pragma unroll
    for (int fm = 0; fm < 4; fm++)
#pragma unroll
        for (int fn = 0; fn < 6; fn++)
#pragma unroll
            for (int e = 0; e < 4; e++) acc[fm][fn][e] = 0.0f;

    float4 xr[4];
    uint4  wh[3], wl[3];
    const int xrow = tid >> 1;
    const int xco  = (tid & 1) * 16;

#define LDCHUNK(c)                                                              \
    do {                                                                        \
        const float* xp = x + (size_t)(m0 + xrow) * DM + (c) * KC + xco;        \
        xr[0] = *(const float4*)(xp + 0);                                       \
        xr[1] = *(const float4*)(xp + 4);                                       \
        xr[2] = *(const float4*)(xp + 8);                                       \
        xr[3] = *(const float4*)(xp + 12);                                      \
        _Pragma("unroll")                                                       \
        for (int q = 0; q < 3; q++) {                                           \
            int idx = tid + q * 256;                                            \
            int wrow = idx >> 2, wch = idx & 3;                                 \
            int u4 = wrow * 128 + (c) * 4 + wch;                                \
            wh[q] = g_Whi4[u4];                                                 \
            wl[q] = g_Wlo4[u4];                                                 \
        }                                                                       \
    } while (0)

#define STCHUNK(buf)                                                            \
    do {                                                                        \
        char* bs = smem + (buf) * STG_SZ;                                       \
        uint4 h0 = make_uint4(hipack(xr[0].x, xr[0].y), hipack(xr[0].z, xr[0].w),\
                              hipack(xr[1].x, xr[1].y), hipack(xr[1].z, xr[1].w));\
        uint4 h1 = make_uint4(hipack(xr[2].x, xr[2].y), hipack(xr[2].z, xr[2].w),\
                              hipack(xr[3].x, xr[3].y), hipack(xr[3].z, xr[3].w));\
        uint4 l0 = make_uint4(lopack(xr[0].x, xr[0].y), lopack(xr[0].z, xr[0].w),\
                              lopack(xr[1].x, xr[1].y), lopack(xr[1].z, xr[1].w));\
        uint4 l1 = make_uint4(lopack(xr[2].x, xr[2].y), lopack(xr[2].z, xr[2].w),\
                              lopack(xr[3].x, xr[3].y), lopack(xr[3].z, xr[3].w));\
        int ach = (tid & 1) * 2;                                                \
        *(uint4*)(bs + A_OFF + xrow * ROWB + ach * 16)        = h0;             \
        *(uint4*)(bs + A_OFF + xrow * ROWB + (ach + 1) * 16)  = h1;             \
        *(uint4*)(bs + A_OFF + A_TERM + xrow * ROWB + ach * 16)       = l0;     \
        *(uint4*)(bs + A_OFF + A_TERM + xrow * ROWB + (ach + 1) * 16) = l1;     \
        _Pragma("unroll")                                                       \
        for (int q = 0; q < 3; q++) {                                           \
            int idx = tid + q * 256;                                            \
            int wrow = idx >> 2, wch = idx & 3;                                 \
            *(uint4*)(bs + B_OFF + wrow * ROWB + wch * 16) = wh[q];             \
            *(uint4*)(bs + B_OFF + B_TERM + wrow * ROWB + wch * 16) = wl[q];    \
        }                                                                       \
    } while (0)

    LDCHUNK(0);
    STCHUNK(0);
    __syncthreads();
    LDCHUNK(1);

    for (int c = 0; c < NKC; c++) {
        const uint32_t bs = sb + (uint32_t)(c & 1) * STG_SZ;
#pragma unroll
        for (int ks = 0; ks < 2; ks++) {
            const int arow_l = (lane & 15);
            const int achk   = ks * 2 + (lane >> 4);
            const int brow_l = (lane & 7) + ((lane >> 4) << 3);
            const int bchk   = ks * 2 + ((lane >> 3) & 1);
#pragma unroll
            for (int term = 0; term < 3; term++) {
                const uint32_t aoff = bs + A_OFF + ((term == 2) ? A_TERM : 0);
                const uint32_t boff = bs + B_OFF + ((term == 1) ? B_TERM : 0);
                uint32_t bfr[6][2];
#pragma unroll
                for (int bn = 0; bn < 3; bn++) {
                    uint32_t r[4];
                    int brow = warp_n * 48 + bn * 16 + brow_l;
                    ldsm4(r, boff + brow * ROWB + bchk * 16);
                    bfr[2 * bn][0] = r[0]; bfr[2 * bn][1] = r[1];
                    bfr[2 * bn + 1][0] = r[2]; bfr[2 * bn + 1][1] = r[3];
                }
#pragma unroll
                for (int fm = 0; fm < 4; fm++) {
                    uint32_t a[4];
                    int arow = warp_m * 64 + fm * 16 + arow_l;
                    ldsm4(a, aoff + arow * ROWB + achk * 16);
#pragma unroll
                    for (int fn = 0; fn < 6; fn++)
                        mma16816(acc[fm][fn], a, bfr[fn]);
                }
            }
        }
        if (c + 1 < NKC) {
            STCHUNK((c + 1) & 1);
            __syncthreads();
            if (c + 2 < NKC) LDCHUNK(c + 2);
        }
    }

    const int g = lane >> 2;
    const int t = lane & 3;
#pragma unroll
    for (int fn = 0; fn < 6; fn++) {
        const int nblk = warp_n * 48 + fn * 8;
        const int n    = nblk + 2 * t;
#pragma unroll
        for (int fm = 0; fm < 4; fm++) {
#pragma unroll
            for (int half = 0; half < 2; half++) {
                const int m = m0 + warp_m * 64 + fm * 16 + g + half * 8;
                float v0 = acc[fm][fn][2 * half + 0];
                float v1 = acc[fm][fn][2 * half + 1];
                if (nblk < 64) {
                    v0 = softplus_f(v0 + bd[n]);
                    v1 = softplus_f(v1 + bd[n + 1]);
                    *(float2*)&g_delta[(size_t)m * NS + n] = make_float2(v0, v1);
                } else if (nblk < 128) {
                    const int j = n - 64;
                    float2 xv = *(const float2*)&x[(size_t)m * DM + j];
                    v0 = (v0 + bb[j]) * xv.x;
                    v1 = (v1 + bb[j + 1]) * xv.y;
                    *(float2*)&g_u[(size_t)m * NS + j] = make_float2(v0, v1);
                } else {
                    const int j = n - 128;
                    v0 += bc[j];
                    v1 += bc[j + 1];
                    *(float2*)&g_c[(size_t)m * NS + j] = make_float2(v0, v1);
                }
            }
        }
    }
}

// ------------------------------- scan pass 1 --------------------------------
// grid 128 (b[8] x chunk[16]), 1024 thr = 32 warps; warp covers 2 i-rows,
// 16 lanes per i, lane owns j in [4g, 4g+4).
__global__ void __launch_bounds__(1024, 1)
scan1_kernel(const float* __restrict__ A_log) {
    __shared__ float su[2][TS][NS];
    __shared__ float sd[2][TS][NS];

    const int tid = threadIdx.x;
    const int w   = tid >> 5;
    const int l   = tid & 31;
    const int isub = l >> 4;         // 0..1
    const int g    = l & 15;         // j-group
    const int bx  = blockIdx.x;
    const int b     = bx >> 4;
    const int chunk = bx & 15;
    const int i     = w * 2 + isub;  // 0..63
    const int row   = b * NS + i;
    const int t0    = chunk * LQ;

    float a[4];
    *(float4*)&a[0] = *(const float4*)&A_log[i * NS + 4 * g];
#pragma unroll
    for (int k = 0; k < 4; k++) a[k] *= LOG2E;

    const float* ubase = g_u + ((size_t)(b * SQ + t0)) * NS;
    const float* dbase = g_delta + ((size_t)(b * SQ + t0)) * NS;

    // staging: group 0 (tid<256) -> su, group 1 -> sd; 1 float4/thread.
    const int grp = tid >> 8;
    const int gid = tid & 255;
    const int ss = gid >> 4, sp = (gid & 15) << 2;

    float4 rs = make_float4(0.f, 0.f, 0.f, 0.f);
    if (grp == 0)      rs = *(const float4*)(ubase + (size_t)ss * NS + sp);
    else if (grp == 1) rs = *(const float4*)(dbase + (size_t)ss * NS + sp);
    if (grp == 0)      *(float4*)&su[0][ss][sp] = rs;
    else if (grp == 1) *(float4*)&sd[0][ss][sp] = rs;
    __syncthreads();

    float h[4] = {0.f, 0.f, 0.f, 0.f};
    float dsum = 0.0f;

    for (int tile = 0; tile < NTIL; tile++) {
        const int cur = tile & 1;
        if (tile + 1 < NTIL) {
            const int toff = (tile + 1) * TS;
            if (grp == 0)      rs = *(const float4*)(ubase + (size_t)(toff + ss) * NS + sp);
            else if (grp == 1) rs = *(const float4*)(dbase + (size_t)(toff + ss) * NS + sp);
        }
#pragma unroll
        for (int s = 0; s < TS; s++) {
            float d = sd[cur][s][i];
            dsum += d;
            float4 uu = *(const float4*)&su[cur][s][4 * g];
            h[0] = ex2(a[0] * d) * h[0] + uu.x;
            h[1] = ex2(a[1] * d) * h[1] + uu.y;
            h[2] = ex2(a[2] * d) * h[2] + uu.z;
            h[3] = ex2(a[3] * d) * h[3] + uu.w;
        }
        if (tile + 1 < NTIL) {
            __syncthreads();
            const int nxt = cur ^ 1;
            if (grp == 0)      *(float4*)&su[nxt][ss][sp] = rs;
            else if (grp == 1) *(float4*)&sd[nxt][ss][sp] = rs;
            __syncthreads();
        }
    }

    *(float4*)&g_hend[((size_t)row * GQ + chunk) * NS + 4 * g] =
        make_float4(h[0], h[1], h[2], h[3]);
    if (g == 0) g_dsum[row * GQ + chunk] = dsum;
}

// ------------------------------- scan pass 3 --------------------------------
__global__ void __launch_bounds__(1024, 1)
scan3_kernel(const float* __restrict__ A_log, float* __restrict__ out) {
    __shared__ float su[2][TS][NS];
    __shared__ float sc[2][TS][NS];
    __shared__ float sd[2][TS][NS];
    __shared__ float ys[2][TS][NS];

    const int tid = threadIdx.x;
    const int w   = tid >> 5;
    const int l   = tid & 31;
    const int isub = l >> 4;
    const int g    = l & 15;
    const int bx  = blockIdx.x;
    const int b     = bx >> 4;
    const int chunk = bx & 15;
    const int i     = w * 2 + isub;
    const int row   = b * NS + i;
    const int t0    = chunk * LQ;

    float a[4];
    *(float4*)&a[0] = *(const float4*)&A_log[i * NS + 4 * g];
#pragma unroll
    for (int k = 0; k < 4; k++) a[k] *= LOG2E;

    const float* ubase = g_u + ((size_t)(b * SQ + t0)) * NS;
    const float* cbase = g_c + ((size_t)(b * SQ + t0)) * NS;
    const float* dbase = g_delta + ((size_t)(b * SQ + t0)) * NS;

    // staging groups: 0 -> su, 1 -> sc, 2 -> sd; 1 float4/thread.
    const int grp = tid >> 8;
    const int gid = tid & 255;
    const int ss = gid >> 4, sp = (gid & 15) << 2;

    float4 rs = make_float4(0.f, 0.f, 0.f, 0.f);
    if (grp == 0)      rs = *(const float4*)(ubase + (size_t)ss * NS + sp);
    else if (grp == 1) rs = *(const float4*)(cbase + (size_t)ss * NS + sp);
    else if (grp == 2) rs = *(const float4*)(dbase + (size_t)ss * NS + sp);
    if (grp == 0)      *(float4*)&su[0][ss][sp] = rs;
    else if (grp == 1) *(float4*)&sc[0][ss][sp] = rs;
    else if (grp == 2) *(float4*)&sd[0][ss][sp] = rs;

    // ---- lookback: h_start = sum_{p<chunk} exp2(a * S_p) * h_end[p] ----
    float h[4] = {0.f, 0.f, 0.f, 0.f};
    {
        float S = 0.0f;
        const float* dsp = g_dsum + row * GQ;
        const float* hep = g_hend + ((size_t)row * GQ) * NS + 4 * g;
        for (int p = chunk - 1; p >= 0; p--) {
            float4 he = *(const float4*)(hep + (size_t)p * NS);
            h[0] += ex2(a[0] * S) * he.x;
            h[1] += ex2(a[1] * S) * he.y;
            h[2] += ex2(a[2] * S) * he.z;
            h[3] += ex2(a[3] * S) * he.w;
            S += dsp[p];
        }
    }
    __syncthreads();

    for (int tile = 0; tile < NTIL; tile++) {
        const int cur = tile & 1;
        if (tile + 1 < NTIL) {
            const int toff = (tile + 1) * TS;
            if (grp == 0)      rs = *(const float4*)(ubase + (size_t)(toff + ss) * NS + sp);
            else if (grp == 1) rs = *(const float4*)(cbase + (size_t)(toff + ss) * NS + sp);
            else if (grp == 2) rs = *(const float4*)(dbase + (size_t)(toff + ss) * NS + sp);
        }
#pragma unroll
        for (int s = 0; s < TS; s++) {
            float d = sd[cur][s][i];
            float4 uu = *(const float4*)&su[cur][s][4 * g];
            float4 cc = *(const float4*)&sc[cur][s][4 * g];
            h[0] = ex2(a[0] * d) * h[0] + uu.x;
            h[1] = ex2(a[1] * d) * h[1] + uu.y;
            h[2] = ex2(a[2] * d) * h[2] + uu.z;
            h[3] = ex2(a[3] * d) * h[3] + uu.w;
            float p = cc.x * h[0] + cc.y * h[1] + cc.z * h[2] + cc.w * h[3];
            p += __shfl_xor_sync(0xffffffffu, p, 8);
            p += __shfl_xor_sync(0xffffffffu, p, 4);
            p += __shfl_xor_sync(0xffffffffu, p, 2);
            p += __shfl_xor_sync(0xffffffffu, p, 1);
            if (g == 0) ys[cur][s][i] = p;
        }
        __syncthreads();      // ys[cur] complete; all reads of smem[cur] done
        if (tile + 1 < NTIL) {
            const int nxt = cur ^ 1;
            if (grp == 0)      *(float4*)&su[nxt][ss][sp] = rs;
            else if (grp == 1) *(float4*)&sc[nxt][ss][sp] = rs;
            else if (grp == 2) *(float4*)&sd[nxt][ss][sp] = rs;
        }
        // coalesced y writeout (threads 0-511): 16 t x 32 float2
        if (tid < 512) {
            const int yt = tid >> 5;
            const int yi = (tid & 31) << 1;
            float2 yv = *(const float2*)&ys[cur][yt][yi];
            const int t = t0 + tile * TS + yt;
            *(float2*)&out[((size_t)(b * SQ + t)) * NS + yi] = yv;
        }
        if (tile + 1 < NTIL) __syncthreads();   // smem[nxt] ready
    }
}

// --------------------------------- launch -----------------------------------
extern "C" void kernel_launch(void* const* d_in, const int* in_sizes, int n_in,
                              void* d_out, int out_size) {
    const float* x  = (const float*)d_in[0];
    const float* Wd = (const float*)d_in[7];
    const float* bd = (const float*)d_in[8];
    const float* Wb = (const float*)d_in[9];
    const float* bb = (const float*)d_in[10];
    const float* Wc = (const float*)d_in[11];
    const float* bc = (const float*)d_in[12];
    const float* A  = (const float*)d_in[13];
    float* out = (float*)d_out;

    cudaFuncSetAttribute(proj_mma_kernel,
                         cudaFuncAttributeMaxDynamicSharedMemorySize, SMEM_MMA);

    wconv_kernel<<<NTOT * DM / 8 / 256, 256>>>(Wd, Wb, Wc);
    proj_mma_kernel<<<ROWS / MT, 256, SMEM_MMA>>>(x, bd, bb, bc);
    scan1_kernel<<<BQ * GQ, 1024>>>(A);
    scan3_kernel<<<BQ * GQ, 1024>>>(A, out);
}